// round 9
// baseline (speedup 1.0000x reference)
#include <cuda_runtime.h>

#define BMAX 16384

__device__ float g_y2[BMAX * 400];    // conv2+pool output, flattened (C,H,W)
__device__ float g_w1T[400 * 128];    // fc_w transposed  [k][c]
__device__ float g_w2T[128 * 64];     // fc2_w transposed [k][c]

__device__ __forceinline__ float4 fma4(float4 a, float4 b, float4 c) {
    return make_float4(fmaf(a.x, b.x, c.x), fmaf(a.y, b.y, c.y),
                       fmaf(a.z, b.z, c.z), fmaf(a.w, b.w, c.w));
}

// ---------------------------------------------------------------------------
// Fused conv kernel, 2 images / 160 threads. Last 200 blocks instead perform
// the FC weight transposes (kT folded in; they return before any sync).
// ---------------------------------------------------------------------------
__global__ void __launch_bounds__(160) k12_conv(const float* __restrict__ x,
                                                const float* __restrict__ w1,
                                                const float* __restrict__ b1,
                                                const float* __restrict__ w2,
                                                const float* __restrict__ b2,
                                                const float* __restrict__ fc_w,
                                                const float* __restrict__ fc2_w) {
    const int t = threadIdx.x;
    const int nconv = gridDim.x - 200;

    if (blockIdx.x >= nconv) {   // ---- transpose role ----
        const int base = (blockIdx.x - nconv) * 160 + t;
        for (int i = base; i < 51200; i += 32000) {
            const int c = i / 400, k = i - c * 400;
            g_w1T[k * 128 + c] = fc_w[i];
        }
        if (base < 8192) {
            const int c = base / 128, k = base - c * 128;
            g_w2T[k * 64 + c] = fc2_w[base];
        }
        return;
    }

    __shared__ __align__(16) float SM[8888];
    float*  Tbuf = SM;                   // [2 img][12 y][8 ic][5 p][4] = 3840
    float*  sx   = SM;                   // [2 img][784] (alias, disjoint lifetime)
    float*  sy1  = SM + 3840;            // [2 img][8 ic][13 y][16] = 3328
    float4* suw4 = (float4*)(SM + 7168); // [16 oc][25] float4
    float4* sw14 = (float4*)(SM + 8768); // [8 oc][3 ky] float4 (w0,w1,w2,0)
    float*  sb1  = SM + 8864;
    float*  sb2  = SM + 8872;

    const int img0 = blockIdx.x * 2;

    // ---- stage 0 ----
    if (t < 24) {
        const int oc = t / 3, ky = t - oc * 3;
        const float* g = w1 + oc * 9 + ky * 3;
        sw14[t] = make_float4(g[0], g[1], g[2], 0.f);
    }
    if (t >= 80 && t < 88)   sb1[t - 80] = b1[t - 80];
    if (t >= 88 && t < 104)  sb2[t - 88] = b2[t - 88];
    for (int i = t; i < 384; i += 160) {         // Winograd weight transform
        const int oc = i / 24, rem = i - oc * 24;
        const int ic = rem / 3, ky = rem - ic * 3;
        const float* g = w2 + oc * 72 + ic * 9 + ky * 3;
        const float a = g[0], bq = g[1], c = g[2];
        suw4[oc * 25 + ic * 3 + ky] =
            make_float4(a, 0.5f * (a + bq + c), 0.5f * (a - bq + c), c);
    }
    {
        const float4* xs = (const float4*)(x + img0 * 784);
        for (int i = t; i < 392; i += 160) ((float4*)sx)[i] = xs[i];
    }
    __syncthreads();

    // ---- phase A: conv1 + bias + relu + pool -> sy1 ----
    for (int i = t; i < 338; i += 160) {
        const int sub = i / 169;
        const int local = i - sub * 169;
        const int py = local / 13, px = local - py * 13;
        const float* xim = sx + sub * 784 + (2 * py) * 28 + 2 * px;

        float win[4][4];
#pragma unroll
        for (int j = 0; j < 4; j++) {
            const float2* rr = (const float2*)(xim + j * 28);
            const float2 a = rr[0], b = rr[1];
            win[j][0] = a.x; win[j][1] = a.y; win[j][2] = b.x; win[j][3] = b.y;
        }

        float* outp = sy1 + sub * 1664 + py * 16 + px;
#pragma unroll
        for (int oc = 0; oc < 8; oc++) {
            float c00 = 0.f, c01 = 0.f, c10 = 0.f, c11 = 0.f;
#pragma unroll
            for (int ky = 0; ky < 3; ky++) {
                const float4 wv = sw14[oc * 3 + ky];
                c00 = fmaf(win[ky][0], wv.x, c00);
                c00 = fmaf(win[ky][1], wv.y, c00);
                c00 = fmaf(win[ky][2], wv.z, c00);
                c01 = fmaf(win[ky][1], wv.x, c01);
                c01 = fmaf(win[ky][2], wv.y, c01);
                c01 = fmaf(win[ky][3], wv.z, c01);
                c10 = fmaf(win[ky + 1][0], wv.x, c10);
                c10 = fmaf(win[ky + 1][1], wv.y, c10);
                c10 = fmaf(win[ky + 1][2], wv.z, c10);
                c11 = fmaf(win[ky + 1][1], wv.x, c11);
                c11 = fmaf(win[ky + 1][2], wv.y, c11);
                c11 = fmaf(win[ky + 1][3], wv.z, c11);
            }
            const float m = fmaxf(fmaxf(c00, c01), fmaxf(c10, c11)) + sb1[oc];
            outp[oc * 208] = fmaxf(m, 0.f);
        }
    }
    __syncthreads();

    // ---- phase B1: input transform ----
    for (int i = t; i < 192; i += 160) {
        const int img = i / 96, rem = i - img * 96;
        const int y = rem / 8, ic = rem - y * 8;
        const float4* rp = (const float4*)(sy1 + img * 1664 + ic * 208 + y * 16);
        float r[12];
#pragma unroll
        for (int m = 0; m < 3; m++) {
            const float4 v = rp[m];
            r[4 * m] = v.x; r[4 * m + 1] = v.y; r[4 * m + 2] = v.z; r[4 * m + 3] = v.w;
        }
        float4* dst = (float4*)(Tbuf + img * 1920 + (y * 8 + ic) * 20);
#pragma unroll
        for (int p = 0; p < 5; p++)
            dst[p] = make_float4(r[2 * p] - r[2 * p + 2],
                                 r[2 * p + 1] + r[2 * p + 2],
                                 r[2 * p + 2] - r[2 * p + 1],
                                 r[2 * p + 1] - r[2 * p + 3]);
    }
    __syncthreads();

    // ---- phase B2: m-space conv2 + pool + bias + relu ----
    const int sub = t / 80;
    const int r = t - sub * 80;
    const int py = r >> 4, oc = r & 15;
    const float* Timg = Tbuf + sub * 1920;
    const float4* wbase = suw4 + oc * 25;

    float4 macc[2][5];
#pragma unroll
    for (int a = 0; a < 2; a++)
#pragma unroll
        for (int p = 0; p < 5; p++) macc[a][p] = make_float4(0.f, 0.f, 0.f, 0.f);

#pragma unroll 2
    for (int ic = 0; ic < 8; ic++) {
        const float4 u0 = wbase[ic * 3 + 0];
        const float4 u1 = wbase[ic * 3 + 1];
        const float4 u2 = wbase[ic * 3 + 2];
#pragma unroll
        for (int s = 0; s < 4; s++) {
            const float4* Trow = (const float4*)(Timg + ((2 * py + s) * 8 + ic) * 20);
            float4 tr[5];
#pragma unroll
            for (int p = 0; p < 5; p++) tr[p] = Trow[p];
            if (s < 3) {
                const float4 u = (s == 0) ? u0 : (s == 1) ? u1 : u2;
#pragma unroll
                for (int p = 0; p < 5; p++) macc[0][p] = fma4(tr[p], u, macc[0][p]);
            }
            if (s >= 1) {
                const float4 u = (s == 1) ? u0 : (s == 2) ? u1 : u2;
#pragma unroll
                for (int p = 0; p < 5; p++) macc[1][p] = fma4(tr[p], u, macc[1][p]);
            }
        }
    }

    float* outp = g_y2 + (img0 + sub) * 400 + oc * 25 + py * 5;
    const float bb = sb2[oc];
#pragma unroll
    for (int p = 0; p < 5; p++) {
        const float o00 = macc[0][p].x + macc[0][p].y + macc[0][p].z;
        const float o01 = macc[0][p].y - macc[0][p].z - macc[0][p].w;
        const float o10 = macc[1][p].x + macc[1][p].y + macc[1][p].z;
        const float o11 = macc[1][p].y - macc[1][p].z - macc[1][p].w;
        const float m = fmaxf(fmaxf(o00, o01), fmaxf(o10, o11));
        outp[p] = fmaxf(m + bb, 0.f);
    }
}

// ---------------------------------------------------------------------------
// Kernel 3: register-tiled FC stack. 16 rows per block, 128 threads.
// Stage 1: thread = (rg=warp, cg=lane) owns 4 rows x 4 cols.
// Stage 2: thread owns 2 rows x 4 cols.
// ---------------------------------------------------------------------------
__global__ void __launch_bounds__(128) k3_fc(const float* __restrict__ fc_b,
                                             const float* __restrict__ fc2_b,
                                             const float* __restrict__ fc3_w,
                                             const float* __restrict__ fc3_b,
                                             float* __restrict__ out) {
    __shared__ __align__(16) float4 sx4[16 * 100];   // X tile [16][400]
    __shared__ __align__(16) float4 sh14[16 * 32];   // h1 [16][128]
    __shared__ __align__(16) float4 sh24[16 * 16];   // h2 [16][64]
    __shared__ __align__(16) float  sw3[640];
    __shared__ float sb3[10];

    const int r0 = blockIdx.x * 16;
    const int t = threadIdx.x;

    {
        const float4* xin = (const float4*)(g_y2 + r0 * 400);
        for (int i = t; i < 1600; i += 128) sx4[i] = xin[i];
        for (int i = t; i < 160; i += 128) ((float4*)sw3)[i] = ((const float4*)fc3_w)[i];
        if (t < 10) sb3[t] = fc3_b[t];
    }
    __syncthreads();

    // ---- stage 1: 4x4 register tile, h1 = relu(X.W1 + b1) ----
    {
        const int cg = t & 31;      // column group: cols cg*4..+3
        const int rg = t >> 5;      // row group (warp): rows rg*4..+3
        float acc[4][4];
#pragma unroll
        for (int r = 0; r < 4; r++)
#pragma unroll
            for (int c = 0; c < 4; c++) acc[r][c] = 0.f;

        for (int k4 = 0; k4 < 100; k4++) {
            float xk[4][4];
#pragma unroll
            for (int r = 0; r < 4; r++) {
                const float4 v = sx4[(rg * 4 + r) * 100 + k4];
                xk[r][0] = v.x; xk[r][1] = v.y; xk[r][2] = v.z; xk[r][3] = v.w;
            }
            float4 wv[4];
#pragma unroll
            for (int kk = 0; kk < 4; kk++)
                wv[kk] = *(const float4*)(g_w1T + (k4 * 4 + kk) * 128 + cg * 4);
#pragma unroll
            for (int kk = 0; kk < 4; kk++)
#pragma unroll
                for (int r = 0; r < 4; r++) {
                    acc[r][0] = fmaf(xk[r][kk], wv[kk].x, acc[r][0]);
                    acc[r][1] = fmaf(xk[r][kk], wv[kk].y, acc[r][1]);
                    acc[r][2] = fmaf(xk[r][kk], wv[kk].z, acc[r][2]);
                    acc[r][3] = fmaf(xk[r][kk], wv[kk].w, acc[r][3]);
                }
        }
        const float4 bv = *(const float4*)(fc_b + cg * 4);
#pragma unroll
        for (int r = 0; r < 4; r++)
            sh14[(rg * 4 + r) * 32 + cg] =
                make_float4(fmaxf(acc[r][0] + bv.x, 0.f),
                            fmaxf(acc[r][1] + bv.y, 0.f),
                            fmaxf(acc[r][2] + bv.z, 0.f),
                            fmaxf(acc[r][3] + bv.w, 0.f));
    }
    __syncthreads();

    // ---- stage 2: 2x4 register tile, h2 = h1.W2 + b2 ----
    {
        const int cg = t & 15;      // cols cg*4..+3 (of 64)
        const int rg = t >> 4;      // rows rg*2, rg*2+1 (of 16)
        float acc[2][4];
#pragma unroll
        for (int r = 0; r < 2; r++)
#pragma unroll
            for (int c = 0; c < 4; c++) acc[r][c] = 0.f;

        for (int k4 = 0; k4 < 32; k4++) {
            float hk[2][4];
#pragma unroll
            for (int r = 0; r < 2; r++) {
                const float4 v = sh14[(rg * 2 + r) * 32 + k4];
                hk[r][0] = v.x; hk[r][1] = v.y; hk[r][2] = v.z; hk[r][3] = v.w;
            }
            float4 wv[4];
#pragma unroll
            for (int kk = 0; kk < 4; kk++)
                wv[kk] = *(const float4*)(g_w2T + (k4 * 4 + kk) * 64 + cg * 4);
#pragma unroll
            for (int kk = 0; kk < 4; kk++)
#pragma unroll
                for (int r = 0; r < 2; r++) {
                    acc[r][0] = fmaf(hk[r][kk], wv[kk].x, acc[r][0]);
                    acc[r][1] = fmaf(hk[r][kk], wv[kk].y, acc[r][1]);
                    acc[r][2] = fmaf(hk[r][kk], wv[kk].z, acc[r][2]);
                    acc[r][3] = fmaf(hk[r][kk], wv[kk].w, acc[r][3]);
                }
        }
        const float4 bv = *(const float4*)(fc2_b + cg * 4);
#pragma unroll
        for (int r = 0; r < 2; r++)
            sh24[(rg * 2 + r) * 16 + cg] =
                make_float4(acc[r][0] + bv.x, acc[r][1] + bv.y,
                            acc[r][2] + bv.z, acc[r][3] + bv.w);
    }
    __syncthreads();

    // ---- stage 3 ----
    const float* sh2 = (const float*)sh24;
    for (int idx = t; idx < 160; idx += 128) {
        const int r = idx / 10, c = idx - r * 10;
        float a = sb3[c];
        const float* h = sh2 + r * 64;
        const float* wv = sw3 + c * 64;
#pragma unroll
        for (int k = 0; k < 64; k++) a = fmaf(h[k], wv[k], a);
        out[(r0 + r) * 10 + c] = a;
    }
}

// ---------------------------------------------------------------------------
extern "C" void kernel_launch(void* const* d_in, const int* in_sizes, int n_in,
                              void* d_out, int out_size) {
    const float* x       = (const float*)d_in[0];
    const float* conv1_w = (const float*)d_in[1];
    const float* conv1_b = (const float*)d_in[2];
    const float* conv2_w = (const float*)d_in[3];
    const float* conv2_b = (const float*)d_in[4];
    const float* fc_w    = (const float*)d_in[5];
    const float* fc_b    = (const float*)d_in[6];
    const float* fc2_w   = (const float*)d_in[7];
    const float* fc2_b   = (const float*)d_in[8];
    const float* fc3_w   = (const float*)d_in[9];
    const float* fc3_b   = (const float*)d_in[10];
    float* out = (float*)d_out;

    const int B = in_sizes[0] / 784;

    k12_conv<<<B / 2 + 200, 160>>>(x, conv1_w, conv1_b, conv2_w, conv2_b,
                                   fc_w, fc2_w);
    k3_fc<<<B / 16, 128>>>(fc_b, fc2_b, fc3_w, fc3_b, out);
}

// round 10
// speedup vs baseline: 1.0763x; 1.0763x over previous
#include <cuda_runtime.h>

#define BMAX 16384

__device__ float g_y2[BMAX * 400];    // conv2+pool output, flattened (C,H,W)
__device__ float g_w1T[400 * 128];    // fc_w packed  [k/4][c][4]
__device__ float g_w2T[128 * 64];     // fc2_w packed [k/4][c][4]

__device__ __forceinline__ float4 fma4(float4 a, float4 b, float4 c) {
    return make_float4(fmaf(a.x, b.x, c.x), fmaf(a.y, b.y, c.y),
                       fmaf(a.z, b.z, c.z), fmaf(a.w, b.w, c.w));
}

// ---------------------------------------------------------------------------
// Fused conv kernel, 2 images / 160 threads. Last 200 blocks instead perform
// the FC weight repack (packed [k/4][c][4]); they return before any sync.
// ---------------------------------------------------------------------------
__global__ void __launch_bounds__(160) k12_conv(const float* __restrict__ x,
                                                const float* __restrict__ w1,
                                                const float* __restrict__ b1,
                                                const float* __restrict__ w2,
                                                const float* __restrict__ b2,
                                                const float* __restrict__ fc_w,
                                                const float* __restrict__ fc2_w) {
    const int t = threadIdx.x;
    const int nconv = gridDim.x - 200;

    if (blockIdx.x >= nconv) {   // ---- repack role ----
        const int base = (blockIdx.x - nconv) * 160 + t;
        for (int i = base; i < 51200; i += 32000) {
            const int c = i / 400, k = i - c * 400;
            g_w1T[(k >> 2) * 512 + c * 4 + (k & 3)] = fc_w[i];
        }
        if (base < 8192) {
            const int c = base / 128, k = base - c * 128;
            g_w2T[(k >> 2) * 256 + c * 4 + (k & 3)] = fc2_w[base];
        }
        return;
    }

    __shared__ __align__(16) float SM[8888];
    float*  Tbuf = SM;                   // [2 img][12 y][8 ic][5 p][4] = 3840
    float*  sx   = SM;                   // [2 img][784] (alias, disjoint lifetime)
    float*  sy1  = SM + 3840;            // [2 img][8 ic][13 y][16] = 3328
    float4* suw4 = (float4*)(SM + 7168); // [16 oc][25] float4
    float4* sw14 = (float4*)(SM + 8768); // [8 oc][3 ky] float4 (w0,w1,w2,0)
    float*  sb1  = SM + 8864;
    float*  sb2  = SM + 8872;

    const int img0 = blockIdx.x * 2;

    // ---- stage 0 ----
    if (t < 24) {
        const int oc = t / 3, ky = t - oc * 3;
        const float* g = w1 + oc * 9 + ky * 3;
        sw14[t] = make_float4(g[0], g[1], g[2], 0.f);
    }
    if (t >= 80 && t < 88)   sb1[t - 80] = b1[t - 80];
    if (t >= 88 && t < 104)  sb2[t - 88] = b2[t - 88];
    for (int i = t; i < 384; i += 160) {         // Winograd weight transform
        const int oc = i / 24, rem = i - oc * 24;
        const int ic = rem / 3, ky = rem - ic * 3;
        const float* g = w2 + oc * 72 + ic * 9 + ky * 3;
        const float a = g[0], bq = g[1], c = g[2];
        suw4[oc * 25 + ic * 3 + ky] =
            make_float4(a, 0.5f * (a + bq + c), 0.5f * (a - bq + c), c);
    }
    {
        const float4* xs = (const float4*)(x + img0 * 784);
        for (int i = t; i < 392; i += 160) ((float4*)sx)[i] = xs[i];
    }
    __syncthreads();

    // ---- phase A: conv1 + bias + relu + pool -> sy1 ----
    for (int i = t; i < 338; i += 160) {
        const int sub = i / 169;
        const int local = i - sub * 169;
        const int py = local / 13, px = local - py * 13;
        const float* xim = sx + sub * 784 + (2 * py) * 28 + 2 * px;

        float win[4][4];
#pragma unroll
        for (int j = 0; j < 4; j++) {
            const float2* rr = (const float2*)(xim + j * 28);
            const float2 a = rr[0], b = rr[1];
            win[j][0] = a.x; win[j][1] = a.y; win[j][2] = b.x; win[j][3] = b.y;
        }

        float* outp = sy1 + sub * 1664 + py * 16 + px;
#pragma unroll
        for (int oc = 0; oc < 8; oc++) {
            float c00 = 0.f, c01 = 0.f, c10 = 0.f, c11 = 0.f;
#pragma unroll
            for (int ky = 0; ky < 3; ky++) {
                const float4 wv = sw14[oc * 3 + ky];
                c00 = fmaf(win[ky][0], wv.x, c00);
                c00 = fmaf(win[ky][1], wv.y, c00);
                c00 = fmaf(win[ky][2], wv.z, c00);
                c01 = fmaf(win[ky][1], wv.x, c01);
                c01 = fmaf(win[ky][2], wv.y, c01);
                c01 = fmaf(win[ky][3], wv.z, c01);
                c10 = fmaf(win[ky + 1][0], wv.x, c10);
                c10 = fmaf(win[ky + 1][1], wv.y, c10);
                c10 = fmaf(win[ky + 1][2], wv.z, c10);
                c11 = fmaf(win[ky + 1][1], wv.x, c11);
                c11 = fmaf(win[ky + 1][2], wv.y, c11);
                c11 = fmaf(win[ky + 1][3], wv.z, c11);
            }
            const float m = fmaxf(fmaxf(c00, c01), fmaxf(c10, c11)) + sb1[oc];
            outp[oc * 208] = fmaxf(m, 0.f);
        }
    }
    __syncthreads();

    // ---- phase B1: input transform ----
    for (int i = t; i < 192; i += 160) {
        const int img = i / 96, rem = i - img * 96;
        const int y = rem / 8, ic = rem - y * 8;
        const float4* rp = (const float4*)(sy1 + img * 1664 + ic * 208 + y * 16);
        float r[12];
#pragma unroll
        for (int m = 0; m < 3; m++) {
            const float4 v = rp[m];
            r[4 * m] = v.x; r[4 * m + 1] = v.y; r[4 * m + 2] = v.z; r[4 * m + 3] = v.w;
        }
        float4* dst = (float4*)(Tbuf + img * 1920 + (y * 8 + ic) * 20);
#pragma unroll
        for (int p = 0; p < 5; p++)
            dst[p] = make_float4(r[2 * p] - r[2 * p + 2],
                                 r[2 * p + 1] + r[2 * p + 2],
                                 r[2 * p + 2] - r[2 * p + 1],
                                 r[2 * p + 1] - r[2 * p + 3]);
    }
    __syncthreads();

    // ---- phase B2: m-space conv2 + pool + bias + relu ----
    const int sub = t / 80;
    const int r = t - sub * 80;
    const int py = r >> 4, oc = r & 15;
    const float* Timg = Tbuf + sub * 1920;
    const float4* wbase = suw4 + oc * 25;

    float4 macc[2][5];
#pragma unroll
    for (int a = 0; a < 2; a++)
#pragma unroll
        for (int p = 0; p < 5; p++) macc[a][p] = make_float4(0.f, 0.f, 0.f, 0.f);

#pragma unroll 2
    for (int ic = 0; ic < 8; ic++) {
        const float4 u0 = wbase[ic * 3 + 0];
        const float4 u1 = wbase[ic * 3 + 1];
        const float4 u2 = wbase[ic * 3 + 2];
#pragma unroll
        for (int s = 0; s < 4; s++) {
            const float4* Trow = (const float4*)(Timg + ((2 * py + s) * 8 + ic) * 20);
            float4 tr[5];
#pragma unroll
            for (int p = 0; p < 5; p++) tr[p] = Trow[p];
            if (s < 3) {
                const float4 u = (s == 0) ? u0 : (s == 1) ? u1 : u2;
#pragma unroll
                for (int p = 0; p < 5; p++) macc[0][p] = fma4(tr[p], u, macc[0][p]);
            }
            if (s >= 1) {
                const float4 u = (s == 1) ? u0 : (s == 2) ? u1 : u2;
#pragma unroll
                for (int p = 0; p < 5; p++) macc[1][p] = fma4(tr[p], u, macc[1][p]);
            }
        }
    }

    float* outp = g_y2 + (img0 + sub) * 400 + oc * 25 + py * 5;
    const float bb = sb2[oc];
#pragma unroll
    for (int p = 0; p < 5; p++) {
        const float o00 = macc[0][p].x + macc[0][p].y + macc[0][p].z;
        const float o01 = macc[0][p].y - macc[0][p].z - macc[0][p].w;
        const float o10 = macc[1][p].x + macc[1][p].y + macc[1][p].z;
        const float o11 = macc[1][p].y - macc[1][p].z - macc[1][p].w;
        const float m = fmaxf(fmaxf(o00, o01), fmaxf(o10, o11));
        outp[p] = fmaxf(m + bb, 0.f);
    }
}

// ---------------------------------------------------------------------------
// Kernel 3 (R7 form — best measured ~75us): fc1+relu, fc2, fc3.
// 16 rows/block, 128 threads; thread t owns column t; broadcast X from smem,
// one packed LDG.128 of weights per k4.
// ---------------------------------------------------------------------------
__global__ void __launch_bounds__(128) k3_fc(const float* __restrict__ fc_b,
                                             const float* __restrict__ fc2_b,
                                             const float* __restrict__ fc3_w,
                                             const float* __restrict__ fc3_b,
                                             float* __restrict__ out) {
    __shared__ __align__(16) float sx[16 * 400];
    __shared__ __align__(16) float sh1[16 * 128];
    __shared__ __align__(16) float sh2[16 * 64];
    __shared__ __align__(16) float sw3[640];
    __shared__ float sb3[10];

    const int r0 = blockIdx.x * 16;
    const int t = threadIdx.x;

    {
        const float4* xin = (const float4*)(g_y2 + r0 * 400);
        for (int i = t; i < 1600; i += 128) ((float4*)sx)[i] = xin[i];
        for (int i = t; i < 160; i += 128) ((float4*)sw3)[i] = ((const float4*)fc3_w)[i];
        if (t < 10) sb3[t] = fc3_b[t];
    }
    __syncthreads();

    // ---- stage 1: h1[r][t] = relu(X[r] . W1[:,t] + fc_b[t]) ----
    {
        float acc[16];
#pragma unroll
        for (int r = 0; r < 16; r++) acc[r] = 0.f;
        const float4* wp = (const float4*)g_w1T + t;   // [k4][128] float4
#pragma unroll 2
        for (int k4 = 0; k4 < 100; k4++) {
            const float4 w4 = wp[k4 * 128];
#pragma unroll
            for (int r = 0; r < 16; r++) {
                const float4 x4 = ((const float4*)sx)[r * 100 + k4];
                acc[r] = fmaf(x4.x, w4.x, acc[r]);
                acc[r] = fmaf(x4.y, w4.y, acc[r]);
                acc[r] = fmaf(x4.z, w4.z, acc[r]);
                acc[r] = fmaf(x4.w, w4.w, acc[r]);
            }
        }
        const float bb = fc_b[t];
#pragma unroll
        for (int r = 0; r < 16; r++)
            sh1[r * 128 + t] = fmaxf(acc[r] + bb, 0.f);
    }
    __syncthreads();

    // ---- stage 2: h2[r][c] = h1[r] . W2[:,c] + fc2_b[c] ----
    {
        const int c = t & 63;
        const int rbase = (t >> 6) * 8;
        float acc[8];
#pragma unroll
        for (int r = 0; r < 8; r++) acc[r] = 0.f;
        const float4* wp = (const float4*)g_w2T + c;   // [k4][64] float4
#pragma unroll 4
        for (int k4 = 0; k4 < 32; k4++) {
            const float4 w4 = wp[k4 * 64];
#pragma unroll
            for (int r = 0; r < 8; r++) {
                const float4 h4 = ((const float4*)sh1)[(rbase + r) * 32 + k4];
                acc[r] = fmaf(h4.x, w4.x, acc[r]);
                acc[r] = fmaf(h4.y, w4.y, acc[r]);
                acc[r] = fmaf(h4.z, w4.z, acc[r]);
                acc[r] = fmaf(h4.w, w4.w, acc[r]);
            }
        }
        const float bb = fc2_b[c];
#pragma unroll
        for (int r = 0; r < 8; r++)
            sh2[(rbase + r) * 64 + c] = acc[r] + bb;
    }
    __syncthreads();

    // ---- stage 3 ----
    for (int idx = t; idx < 160; idx += 128) {
        const int r = idx / 10, c = idx - r * 10;
        float a = sb3[c];
        const float* h = sh2 + r * 64;
        const float* wv = sw3 + c * 64;
#pragma unroll
        for (int k = 0; k < 64; k++) a = fmaf(h[k], wv[k], a);
        out[(r0 + r) * 10 + c] = a;
    }
}

// ---------------------------------------------------------------------------
extern "C" void kernel_launch(void* const* d_in, const int* in_sizes, int n_in,
                              void* d_out, int out_size) {
    const float* x       = (const float*)d_in[0];
    const float* conv1_w = (const float*)d_in[1];
    const float* conv1_b = (const float*)d_in[2];
    const float* conv2_w = (const float*)d_in[3];
    const float* conv2_b = (const float*)d_in[4];
    const float* fc_w    = (const float*)d_in[5];
    const float* fc_b    = (const float*)d_in[6];
    const float* fc2_w   = (const float*)d_in[7];
    const float* fc2_b   = (const float*)d_in[8];
    const float* fc3_w   = (const float*)d_in[9];
    const float* fc3_b   = (const float*)d_in[10];
    float* out = (float*)d_out;

    const int B = in_sizes[0] / 784;

    k12_conv<<<B / 2 + 200, 160>>>(x, conv1_w, conv1_b, conv2_w, conv2_b,
                                   fc_w, fc2_w);
    k3_fc<<<B / 16, 128>>>(fc_b, fc2_b, fc3_w, fc3_b, out);
}